// round 1
// baseline (speedup 1.0000x reference)
#include <cuda_runtime.h>

#define B_ 32
#define S_ 2048
#define D_ 1024
#define E_ 64
#define K_ 8
#define T_ 128   // N_TAGS

// Scratch (allocation-free rule: __device__ globals)
__device__ float g_ent[B_ * E_ * D_];   // 8 MB pooled entity embeddings
__device__ float g_wt[D_ * T_];         // 512 KB transposed fc_w: [D][T]

// ---------------------------------------------------------------------------
// Kernel A: gather + masked mean pool.  One block per (b,e). 256 thr x float4.
// ---------------------------------------------------------------------------
__global__ __launch_bounds__(256) void pool_kernel(
    const float* __restrict__ hs,      // [B,S,D]
    const int*   __restrict__ idx,     // [B,E,K]
    const int*   __restrict__ counts,  // [B,E]
    const int*   __restrict__ nent)    // [B]
{
    int be = blockIdx.x;           // 0..2047
    int b  = be >> 6;
    int e  = be & 63;
    int cnt = counts[be];
    bool active = (e < nent[b]);
    int t = threadIdx.x;           // 256 threads, 4 floats each

    float4 acc = make_float4(0.f, 0.f, 0.f, 0.f);
    if (active) {
        const float* base = hs + (size_t)b * (S_ * D_);
        #pragma unroll
        for (int k = 0; k < K_; ++k) {
            if (k < cnt) {
                int row = idx[be * K_ + k];
                float4 v = *(const float4*)(base + (size_t)row * D_ + t * 4);
                acc.x += v.x; acc.y += v.y; acc.z += v.z; acc.w += v.w;
            }
        }
        float inv = 1.0f / (float)cnt;
        acc.x *= inv; acc.y *= inv; acc.z *= inv; acc.w *= inv;
    }
    *(float4*)(g_ent + (size_t)be * D_ + t * 4) = acc;
}

// ---------------------------------------------------------------------------
// Kernel T: transpose fc_w [T,D] -> g_wt [D,T] (standard 32x32 smem tile).
// ---------------------------------------------------------------------------
__global__ __launch_bounds__(256) void transpose_kernel(const float* __restrict__ W)
{
    __shared__ float tile[32][33];
    int bx = blockIdx.x;   // over D: 1024/32 = 32
    int by = blockIdx.y;   // over T: 128/32  = 4
    int x = threadIdx.x;   // 32
    int y = threadIdx.y;   // 8
    #pragma unroll
    for (int j = 0; j < 4; ++j)
        tile[y + j * 8][x] = W[(size_t)(by * 32 + y + j * 8) * D_ + bx * 32 + x];
    __syncthreads();
    #pragma unroll
    for (int j = 0; j < 4; ++j)
        g_wt[(size_t)(bx * 32 + y + j * 8) * T_ + by * 32 + x] = tile[x][y + j * 8];
}

// ---------------------------------------------------------------------------
// Kernel B: logits[2048,128] = g_ent[2048,1024] @ g_wt[1024,128] + bias
// BM=16, BN=128, BK=64; 128 blocks x 256 threads; 2x4 micro-tile per thread.
// ---------------------------------------------------------------------------
__global__ __launch_bounds__(256) void gemm_kernel(
    const float* __restrict__ bias,    // [T]
    float*       __restrict__ out)     // [B*E, T]
{
    __shared__ float sA[16][64];       // 4 KB, row-major [row][k]
    __shared__ float sW[64][128];      // 32 KB, k-major  [k][col]

    int tid   = threadIdx.x;
    int row0  = blockIdx.x * 16;
    int row_g = tid >> 5;              // 0..7  -> rows row_g*2, row_g*2+1
    int col_g = tid & 31;              // 0..31 -> cols col_g*4 .. +3

    float acc00 = 0.f, acc01 = 0.f, acc02 = 0.f, acc03 = 0.f;
    float acc10 = 0.f, acc11 = 0.f, acc12 = 0.f, acc13 = 0.f;

    for (int k0 = 0; k0 < D_; k0 += 64) {
        // Load A tile: 16 rows x 64 k = 256 float4, one per thread.
        {
            int r  = tid >> 4;         // 0..15
            int kq = tid & 15;         // 0..15
            float4 v = *(const float4*)(g_ent + (size_t)(row0 + r) * D_ + k0 + kq * 4);
            *(float4*)&sA[r][kq * 4] = v;
        }
        // Load W tile: 64 k x 128 cols = 2048 float4, 8 per thread (coalesced).
        #pragma unroll
        for (int it = 0; it < 8; ++it) {
            int i2 = it * 256 + tid;
            int kr = i2 >> 5;          // 0..63
            int cq = i2 & 31;          // 0..31
            float4 v = *(const float4*)(g_wt + (size_t)(k0 + kr) * T_ + cq * 4);
            *(float4*)&sW[kr][cq * 4] = v;
        }
        __syncthreads();

        #pragma unroll
        for (int kk = 0; kk < 64; ++kk) {
            float a0 = sA[row_g * 2 + 0][kk];   // warp-broadcast
            float a1 = sA[row_g * 2 + 1][kk];
            float4 w = *(const float4*)&sW[kk][col_g * 4];   // LDS.128
            acc00 += a0 * w.x; acc01 += a0 * w.y; acc02 += a0 * w.z; acc03 += a0 * w.w;
            acc10 += a1 * w.x; acc11 += a1 * w.y; acc12 += a1 * w.z; acc13 += a1 * w.w;
        }
        __syncthreads();
    }

    float4 bb = *(const float4*)(bias + col_g * 4);
    {
        float4 o;
        o.x = acc00 + bb.x; o.y = acc01 + bb.y; o.z = acc02 + bb.z; o.w = acc03 + bb.w;
        *(float4*)(out + (size_t)(row0 + row_g * 2 + 0) * T_ + col_g * 4) = o;
    }
    {
        float4 o;
        o.x = acc10 + bb.x; o.y = acc11 + bb.y; o.z = acc12 + bb.z; o.w = acc13 + bb.w;
        *(float4*)(out + (size_t)(row0 + row_g * 2 + 1) * T_ + col_g * 4) = o;
    }
}

// ---------------------------------------------------------------------------
extern "C" void kernel_launch(void* const* d_in, const int* in_sizes, int n_in,
                              void* d_out, int out_size)
{
    const float* hs     = (const float*)d_in[0];   // hidden_states [B,S,D]
    const int*   idx    = (const int*)  d_in[1];   // subw_indices  [B,E,K]
    const int*   counts = (const int*)  d_in[2];   // subw_counts   [B,E]
    const int*   nent   = (const int*)  d_in[3];   // num_entities  [B]
    const float* fcw    = (const float*)d_in[4];   // fc_w [T,D]
    const float* fcb    = (const float*)d_in[5];   // fc_b [T]
    float*       out    = (float*)d_out;           // [B,E,T]

    pool_kernel<<<B_ * E_, 256>>>(hs, idx, counts, nent);
    transpose_kernel<<<dim3(D_ / 32, T_ / 32), dim3(32, 8)>>>(fcw);
    gemm_kernel<<<(B_ * E_) / 16, 256>>>(fcb, out);
}

// round 2
// speedup vs baseline: 1.3490x; 1.3490x over previous
#include <cuda_runtime.h>

#define B_ 32
#define S_ 2048
#define D_ 1024
#define E_ 64
#define K_ 8
#define T_ 128       // N_TAGS
#define NSPLIT 8
#define KCHUNK (D_ / NSPLIT)   // 128
#define BK 32
#define BM 64

// Scratch (allocation-free rule: __device__ globals)
__device__ float g_ent[B_ * E_ * D_];            // 8 MB pooled embeddings
__device__ float g_wt[D_ * T_];                  // 512 KB fc_w transposed [D][T]
__device__ float g_part[NSPLIT * B_ * E_ * T_];  // 8 MB k-split partials

// ---- packed f32x2 helpers (sm_103a) --------------------------------------
__device__ __forceinline__ unsigned long long pack2(float a) {
    unsigned long long r;
    asm("mov.b64 %0, {%1, %1};" : "=l"(r) : "f"(a));
    return r;
}
__device__ __forceinline__ void ffma2(unsigned long long& d,
                                      unsigned long long a,
                                      unsigned long long b) {
    asm("fma.rn.f32x2 %0, %1, %2, %3;" : "=l"(d) : "l"(a), "l"(b), "l"(d));
}

// ---------------------------------------------------------------------------
// Kernel A: gather + masked mean pool.  One block per (b,e). 256 thr x float4.
// ---------------------------------------------------------------------------
__global__ __launch_bounds__(256) void pool_kernel(
    const float* __restrict__ hs,      // [B,S,D]
    const int*   __restrict__ idx,     // [B,E,K]
    const int*   __restrict__ counts,  // [B,E]
    const int*   __restrict__ nent)    // [B]
{
    int be = blockIdx.x;
    int b  = be >> 6;
    int e  = be & 63;
    int cnt = counts[be];
    bool active = (e < nent[b]);
    int t = threadIdx.x;

    float4 acc = make_float4(0.f, 0.f, 0.f, 0.f);
    if (active) {
        const float* base = hs + (size_t)b * (S_ * D_);
        #pragma unroll
        for (int k = 0; k < K_; ++k) {
            if (k < cnt) {
                int row = idx[be * K_ + k];
                float4 v = *(const float4*)(base + (size_t)row * D_ + t * 4);
                acc.x += v.x; acc.y += v.y; acc.z += v.z; acc.w += v.w;
            }
        }
        float inv = 1.0f / (float)cnt;
        acc.x *= inv; acc.y *= inv; acc.z *= inv; acc.w *= inv;
    }
    *(float4*)(g_ent + (size_t)be * D_ + t * 4) = acc;
}

// ---------------------------------------------------------------------------
// Kernel T: transpose fc_w [T,D] -> g_wt [D,T].
// ---------------------------------------------------------------------------
__global__ __launch_bounds__(256) void transpose_kernel(const float* __restrict__ W)
{
    __shared__ float tile[32][33];
    int bx = blockIdx.x;   // over D: 32
    int by = blockIdx.y;   // over T: 4
    int x = threadIdx.x;   // 32
    int y = threadIdx.y;   // 8
    #pragma unroll
    for (int j = 0; j < 4; ++j)
        tile[y + j * 8][x] = W[(size_t)(by * 32 + y + j * 8) * D_ + bx * 32 + x];
    __syncthreads();
    #pragma unroll
    for (int j = 0; j < 4; ++j)
        g_wt[(size_t)(bx * 32 + y + j * 8) * T_ + by * 32 + x] = tile[x][y + j * 8];
}

// ---------------------------------------------------------------------------
// Kernel B: k-split GEMM partials.
// grid = (32 m-blocks, 8 k-splits), block = 256 threads.
// BM=64, BN=128, BK=32; per-thread 4 rows x 8 cols via f32x2 FMA.
// ---------------------------------------------------------------------------
__global__ __launch_bounds__(256) void gemm_kernel()
{
    __shared__ __align__(16) float sA[BM][36];    // [row][k], pad keeps 16B align
    __shared__ __align__(16) float sW[BK][132];   // [k][col]

    int tid   = threadIdx.x;
    int mblk  = blockIdx.x;
    int split = blockIdx.y;
    int row0  = (tid >> 4) * 4;        // 0..60
    int col0  = (tid & 15) * 8;        // 0..120
    int k0base = split * KCHUNK;

    unsigned long long acc[4][4];
    #pragma unroll
    for (int i = 0; i < 4; ++i)
        #pragma unroll
        for (int p = 0; p < 4; ++p) acc[i][p] = 0ULL;

    #pragma unroll 1
    for (int t4 = 0; t4 < KCHUNK / BK; ++t4) {
        int k0 = k0base + t4 * BK;

        // A tile: 64 rows x 32 k = 512 float4, 2 per thread
        {
            int i0 = tid;
            int i1 = tid + 256;
            int r0 = i0 >> 3, kq0 = i0 & 7;
            int r1 = i1 >> 3, kq1 = i1 & 7;
            float4 v0 = *(const float4*)(g_ent + (size_t)(mblk * BM + r0) * D_ + k0 + kq0 * 4);
            float4 v1 = *(const float4*)(g_ent + (size_t)(mblk * BM + r1) * D_ + k0 + kq1 * 4);
            *(float4*)&sA[r0][kq0 * 4] = v0;
            *(float4*)&sA[r1][kq1 * 4] = v1;
        }
        // W tile: 32 k x 128 cols = 1024 float4, 4 per thread (coalesced)
        #pragma unroll
        for (int it = 0; it < 4; ++it) {
            int i2 = it * 256 + tid;
            int kr = i2 >> 5;
            int cq = i2 & 31;
            float4 v = *(const float4*)(g_wt + (size_t)(k0 + kr) * T_ + cq * 4);
            *(float4*)&sW[kr][cq * 4] = v;
        }
        __syncthreads();

        #pragma unroll
        for (int g = 0; g < BK / 4; ++g) {
            float4 rA[4];
            #pragma unroll
            for (int i = 0; i < 4; ++i)
                rA[i] = *(const float4*)&sA[row0 + i][g * 4];

            #pragma unroll
            for (int j = 0; j < 4; ++j) {
                ulonglong2 w0 = *(const ulonglong2*)&sW[g * 4 + j][col0];
                ulonglong2 w1 = *(const ulonglong2*)&sW[g * 4 + j][col0 + 4];
                #pragma unroll
                for (int i = 0; i < 4; ++i) {
                    float aj = (j == 0) ? rA[i].x : (j == 1) ? rA[i].y
                             : (j == 2) ? rA[i].z : rA[i].w;
                    unsigned long long a2 = pack2(aj);
                    ffma2(acc[i][0], a2, w0.x);
                    ffma2(acc[i][1], a2, w0.y);
                    ffma2(acc[i][2], a2, w1.x);
                    ffma2(acc[i][3], a2, w1.y);
                }
            }
        }
        __syncthreads();
    }

    float* outp = g_part + (size_t)split * (B_ * E_ * T_);
    #pragma unroll
    for (int i = 0; i < 4; ++i) {
        ulonglong2 v0, v1;
        v0.x = acc[i][0]; v0.y = acc[i][1];
        v1.x = acc[i][2]; v1.y = acc[i][3];
        size_t base = (size_t)(mblk * BM + row0 + i) * T_ + col0;
        *(ulonglong2*)(outp + base)     = v0;
        *(ulonglong2*)(outp + base + 4) = v1;
    }
}

// ---------------------------------------------------------------------------
// Kernel R: reduce 8 partials + bias -> out.
// ---------------------------------------------------------------------------
__global__ __launch_bounds__(256) void reduce_kernel(
    const float* __restrict__ bias, float* __restrict__ out)
{
    int idx = blockIdx.x * 256 + threadIdx.x;       // float4 index, 65536 total
    int t4  = idx & (T_ / 4 - 1);
    float4 s = ((const float4*)bias)[t4];
    #pragma unroll
    for (int sp = 0; sp < NSPLIT; ++sp) {
        float4 v = *(const float4*)(g_part + (size_t)sp * (B_ * E_ * T_) + (size_t)idx * 4);
        s.x += v.x; s.y += v.y; s.z += v.z; s.w += v.w;
    }
    ((float4*)out)[idx] = s;
}

// ---------------------------------------------------------------------------
extern "C" void kernel_launch(void* const* d_in, const int* in_sizes, int n_in,
                              void* d_out, int out_size)
{
    const float* hs     = (const float*)d_in[0];
    const int*   idx    = (const int*)  d_in[1];
    const int*   counts = (const int*)  d_in[2];
    const int*   nent   = (const int*)  d_in[3];
    const float* fcw    = (const float*)d_in[4];
    const float* fcb    = (const float*)d_in[5];
    float*       out    = (float*)d_out;

    pool_kernel<<<B_ * E_, 256>>>(hs, idx, counts, nent);
    transpose_kernel<<<dim3(D_ / 32, T_ / 32), dim3(32, 8)>>>(fcw);
    gemm_kernel<<<dim3(B_ * E_ / BM, NSPLIT), 256>>>();
    reduce_kernel<<<(B_ * E_ * T_ / 4) / 256, 256>>>(fcb, out);
}